// round 8
// baseline (speedup 1.0000x reference)
#include <cuda_runtime.h>
#include <cuda_fp16.h>

typedef unsigned int u32;

// Problem constants: grid (1, C, S, S, S), N points.
#define GS 160
#define GC 12
#define NPTS_MAX 2000000
#define NB (GS * GS * 20)            // bins: (d0,h0, w0>>3) -> 512000
#define ROWB (GS * GC * 2)           // bytes per (d,h) row in interleaved layout: 3840
#define SLABB (GS * ROWB)            // bytes per d-slab: 614400
#define CH_STRIDE (GS * GS * GS)     // channel stride in source layout (floats)

// ---------------- device scratch (module-load allocated) ----------------
// fp16 channel-interleaved UNPADDED grid [D][H][W][12] = 98.3MB (+pad for
// the 64B aligned-window over-read at the array end).
__device__ __half g_ilv[(long long)GS * GS * GS * GC + 128];
__device__ int    d_hist[NB];
__device__ int    d_bsums[512];
// sorted records: (fd, fh, fw, voxel-index-as-int)
__device__ float4 d_sorted[NPTS_MAX];
__device__ int    d_sidx[NPTS_MAX];     // original point index per sorted slot

// ---------------------------------------------------------------------------
// Shared cell math (identical in hist & scatter so counts match assignments).
// ---------------------------------------------------------------------------
struct Cell { int d0, h0, w0; float fd, fh, fw; };

__device__ __forceinline__ Cell cell_of(
    float px, float py, float pz,
    const float* __restrict__ xyz_min, const float* __restrict__ xyz_max)
{
    const float mn0 = __ldg(&xyz_min[0]);
    const float mn1 = __ldg(&xyz_min[1]);
    const float mn2 = __ldg(&xyz_min[2]);
    const float mx0 = __ldg(&xyz_max[0]);
    const float mx1 = __ldg(&xyz_max[1]);
    const float mx2 = __ldg(&xyz_max[2]);

    const float hi  = (float)(GS - 1);   // 159
    const float hi2 = (float)(GS - 2);   // 158

    Cell c;
    float ud = (px - mn0) * (hi / (mx0 - mn0));
    ud = fminf(fmaxf(ud, 0.0f), hi);
    float d0f = fminf(floorf(ud), hi2);
    c.fd = ud - d0f; c.d0 = (int)d0f;

    float uh = (py - mn1) * (hi / (mx1 - mn1));
    uh = fminf(fmaxf(uh, 0.0f), hi);
    float h0f = fminf(floorf(uh), hi2);
    c.fh = uh - h0f; c.h0 = (int)h0f;

    float uw = (pz - mn2) * (hi / (mx2 - mn2));
    uw = fminf(fmaxf(uw, 0.0f), hi);
    float w0f = fminf(floorf(uw), hi2);
    c.fw = uw - w0f; c.w0 = (int)w0f;
    return c;
}

__device__ __forceinline__ int bin_of(const Cell& c) {
    return (c.d0 * GS + c.h0) * 20 + (c.w0 >> 3);
}

// ---------------------------------------------------------------------------
// Kernel 0: zero histogram.
// ---------------------------------------------------------------------------
__global__ void zero_hist_kernel() {
    int i = blockIdx.x * blockDim.x + threadIdx.x;
    if (i < NB) d_hist[i] = 0;
}

// ---------------------------------------------------------------------------
// Kernel 1: transpose+convert [C,D,H,W] f32 -> [D,H,W,12] f16 (24B voxels).
// One block per (d,h) row. Read 12x40 float4; write one contiguous 3840B run.
// ---------------------------------------------------------------------------
__global__ void __launch_bounds__(256) transpose_ilv_kernel(const float* __restrict__ grid) {
    __shared__ float tile[GC][GS + 1];        // padded: conflict-free column reads
    __shared__ u32 rowu[GS * GC / 2];         // 960 uints = the packed 3840B row

    const int row = blockIdx.x;               // row = d*GS + h
    const float* src = grid + (long long)row * GS;

    for (int idx = threadIdx.x; idx < GC * (GS / 4); idx += blockDim.x) {
        int c = idx / (GS / 4);
        int v = idx - c * (GS / 4);
        float4 x = *reinterpret_cast<const float4*>(src + (long long)c * CH_STRIDE + v * 4);
        tile[c][4 * v + 0] = x.x;
        tile[c][4 * v + 1] = x.y;
        tile[c][4 * v + 2] = x.z;
        tile[c][4 * v + 3] = x.w;
    }
    __syncthreads();

    // pack: voxel w occupies uints [w*6, w*6+6); uint i holds ch(2i), ch(2i+1)
    for (int t = threadIdx.x; t < GS * 6; t += blockDim.x) {
        int w = t / 6;
        int i = t - 6 * w;
        __half2 h = __floats2half2_rn(tile[2 * i][w], tile[2 * i + 1][w]);
        rowu[t] = *reinterpret_cast<const u32*>(&h);
    }
    __syncthreads();

    uint4* dst = reinterpret_cast<uint4*>(reinterpret_cast<char*>(g_ilv) + (long long)row * ROWB);
    const uint4* srcu = reinterpret_cast<const uint4*>(rowu);
    for (int j = threadIdx.x; j < ROWB / 16; j += blockDim.x)   // 240 uint4
        dst[j] = srcu[j];
}

// ---------------------------------------------------------------------------
// Kernel 2: histogram over bins.
// ---------------------------------------------------------------------------
__global__ void __launch_bounds__(256) hist_kernel(
    const float* __restrict__ xyz,
    const float* __restrict__ xyz_min,
    const float* __restrict__ xyz_max,
    int N)
{
    int n = blockIdx.x * blockDim.x + threadIdx.x;
    if (n >= N) return;
    Cell c = cell_of(xyz[3 * n], xyz[3 * n + 1], xyz[3 * n + 2], xyz_min, xyz_max);
    atomicAdd(&d_hist[bin_of(c)], 1);
}

// ---------------------------------------------------------------------------
// Kernels 3-5: exclusive scan of d_hist (NB = 500 * 1024).
// ---------------------------------------------------------------------------
__global__ void __launch_bounds__(1024) scan1_kernel() {
    __shared__ int s[1024];
    int gi = blockIdx.x * 1024 + threadIdx.x;
    int v = d_hist[gi];
    s[threadIdx.x] = v;
    __syncthreads();
    for (int off = 1; off < 1024; off <<= 1) {
        int add = (threadIdx.x >= off) ? s[threadIdx.x - off] : 0;
        __syncthreads();
        s[threadIdx.x] += add;
        __syncthreads();
    }
    d_hist[gi] = s[threadIdx.x] - v;          // exclusive
    if (threadIdx.x == 1023) d_bsums[blockIdx.x] = s[1023];
}

__global__ void __launch_bounds__(512) scan2_kernel() {
    __shared__ int s[512];
    int v = (threadIdx.x < NB / 1024) ? d_bsums[threadIdx.x] : 0;
    s[threadIdx.x] = v;
    __syncthreads();
    for (int off = 1; off < 512; off <<= 1) {
        int add = (threadIdx.x >= off) ? s[threadIdx.x - off] : 0;
        __syncthreads();
        s[threadIdx.x] += add;
        __syncthreads();
    }
    if (threadIdx.x < NB / 1024) d_bsums[threadIdx.x] = s[threadIdx.x] - v;  // exclusive
}

__global__ void __launch_bounds__(1024) scan3_kernel() {
    int gi = blockIdx.x * 1024 + threadIdx.x;
    d_hist[gi] += d_bsums[blockIdx.x];
}

// ---------------------------------------------------------------------------
// Kernel 6: scatter. Stores precomputed interp state: (fd, fh, fw, vox) and
// the original index, in bin-sorted order.
// ---------------------------------------------------------------------------
__global__ void __launch_bounds__(256) scatter_kernel(
    const float* __restrict__ xyz,
    const float* __restrict__ xyz_min,
    const float* __restrict__ xyz_max,
    int N)
{
    int n = blockIdx.x * blockDim.x + threadIdx.x;
    if (n >= N) return;
    Cell c = cell_of(xyz[3 * n], xyz[3 * n + 1], xyz[3 * n + 2], xyz_min, xyz_max);
    int pos = atomicAdd(&d_hist[bin_of(c)], 1);
    int vox = (c.d0 * GS + c.h0) * GS + c.w0;
    d_sorted[pos] = make_float4(c.fd, c.fh, c.fw, __int_as_float(vox));
    d_sidx[pos] = n;
}

// ---------------------------------------------------------------------------
// Kernel 7: trilinear gather over sorted points, scattered output.
// Per point: 4 (d,h) row-pairs; each pair = 48B inside a 64B aligned window
// (4 LDG.128, branchless; sel = vox&1 picks the 12 live uints).
// ---------------------------------------------------------------------------
__device__ __forceinline__ void accum_pair(
    float* acc, const uint4* rp, int sel, float wA, float wB)
{
    const u32* u = reinterpret_cast<const u32*>(rp);
    u32 v[12];
#pragma unroll
    for (int i = 0; i < 12; i++) v[i] = sel ? u[i + 2] : u[i];
    // v[0..5] = voxel w0 (ch0..11), v[6..11] = voxel w1
#pragma unroll
    for (int i = 0; i < 6; i++) {
        float2 a = __half22float2(*reinterpret_cast<const __half2*>(&v[i]));
        float2 b = __half22float2(*reinterpret_cast<const __half2*>(&v[6 + i]));
        acc[2 * i + 0] += wA * a.x + wB * b.x;
        acc[2 * i + 1] += wA * a.y + wB * b.y;
    }
}

__global__ void __launch_bounds__(256) trilerp_kernel(float* __restrict__ out, int N)
{
    const int n = blockIdx.x * blockDim.x + threadIdx.x;
    if (n >= N) return;

    const float4 rec = d_sorted[n];
    const int idx = d_sidx[n];
    const float fd = rec.x, fh = rec.y, fw = rec.z;
    const u32 vox = (u32)__float_as_int(rec.w);

    const int sel = (int)(vox & 1u);
    const u32 b0 = vox * 24u - (sel ? 8u : 0u);   // 16B-aligned window start

    const float omfd = 1.0f - fd, omfh = 1.0f - fh, omfw = 1.0f - fw;
    const float coef[4] = { omfd * omfh, omfd * fh, fd * omfh, fd * fh };
    const u32 offs[4] = { b0, b0 + ROWB, b0 + SLABB, b0 + SLABB + ROWB };

    // Batch all 16 LDG.128 for MLP.
    uint4 r[4][4];
#pragma unroll
    for (int p = 0; p < 4; p++) {
        const uint4* q = reinterpret_cast<const uint4*>(
            reinterpret_cast<const char*>(g_ilv) + offs[p]);
        r[p][0] = q[0]; r[p][1] = q[1]; r[p][2] = q[2]; r[p][3] = q[3];
    }

    float acc[12];
#pragma unroll
    for (int i = 0; i < 12; i++) acc[i] = 0.0f;

#pragma unroll
    for (int p = 0; p < 4; p++)
        accum_pair(acc, r[p], sel, coef[p] * omfw, coef[p] * fw);

    float4* o = reinterpret_cast<float4*>(out + (long long)idx * GC);
    o[0] = make_float4(acc[0], acc[1], acc[2], acc[3]);
    o[1] = make_float4(acc[4], acc[5], acc[6], acc[7]);
    o[2] = make_float4(acc[8], acc[9], acc[10], acc[11]);
}

// ---------------------------------------------------------------------------
// kernel_launch
// Inputs (metadata order): xyz [N,3] f32, grid [1,12,160,160,160] f32,
//                          xyz_min [3] f32, xyz_max [3] f32
// Output: [N, 12] f32
// ---------------------------------------------------------------------------
extern "C" void kernel_launch(void* const* d_in, const int* in_sizes, int n_in,
                              void* d_out, int out_size) {
    const float* xyz     = (const float*)d_in[0];
    const float* grid    = (const float*)d_in[1];
    const float* xyz_min = (const float*)d_in[2];
    const float* xyz_max = (const float*)d_in[3];
    float* out = (float*)d_out;

    const int N = in_sizes[0] / 3;
    const int pb = (N + 255) / 256;

    zero_hist_kernel<<<(NB + 255) / 256, 256>>>();
    transpose_ilv_kernel<<<GS * GS, 256>>>(grid);
    hist_kernel<<<pb, 256>>>(xyz, xyz_min, xyz_max, N);
    scan1_kernel<<<NB / 1024, 1024>>>();
    scan2_kernel<<<1, 512>>>();
    scan3_kernel<<<NB / 1024, 1024>>>();
    scatter_kernel<<<pb, 256>>>(xyz, xyz_min, xyz_max, N);
    trilerp_kernel<<<pb, 256>>>(out, N);
}

// round 9
// speedup vs baseline: 1.8340x; 1.8340x over previous
#include <cuda_runtime.h>
#include <cuda_fp16.h>

typedef unsigned int u32;

// Problem constants: grid (1, C, S, S, S), N points.
#define GS 160
#define GC 12
#define VOXH 16                       // padded halves per voxel (32 bytes)
#define VOXB 32                       // bytes per voxel
#define CH_STRIDE (GS * GS * GS)      // channel stride in source layout (floats)
#define ROWB (GS * VOXB)              // h-stride in bytes: 5120
#define SLABB (GS * GS * VOXB)        // d-stride in bytes: 819200

// Scratch: fp16 channel-interleaved padded grid [D][H][W][16]. 131 MB.
__device__ __half g_ilv[(long long)GS * GS * GS * VOXH];

// ---------------------------------------------------------------------------
// Kernel 1: transpose+convert [C,D,H,W] f32 -> [D,H,W,16] f16.
// One block per (d,h) row: read 12 rows as float4 (40 LDG.128 each),
// write 160 voxels of 32B each (contiguous 5120B run). (R3-proven, ~61us)
// ---------------------------------------------------------------------------
__global__ void __launch_bounds__(256) transpose_ilv_kernel(const float* __restrict__ grid) {
    __shared__ float tile[GC][GS];
    const int row = blockIdx.x;          // row = d*GS + h
    const float* src = grid + (long long)row * GS;

    for (int idx = threadIdx.x; idx < GC * (GS / 4); idx += blockDim.x) {
        int c = idx / (GS / 4);
        int v = idx - c * (GS / 4);
        float4 x = *reinterpret_cast<const float4*>(src + (long long)c * CH_STRIDE + v * 4);
        tile[c][4 * v + 0] = x.x;
        tile[c][4 * v + 1] = x.y;
        tile[c][4 * v + 2] = x.z;
        tile[c][4 * v + 3] = x.w;
    }
    __syncthreads();

    if (threadIdx.x < GS) {
        const int w = threadIdx.x;
        __half2 v[8];
#pragma unroll
        for (int i = 0; i < 6; i++)
            v[i] = __floats2half2_rn(tile[2 * i][w], tile[2 * i + 1][w]);
        v[6] = __floats2half2_rn(0.f, 0.f);
        v[7] = v[6];
        uint4* dst = reinterpret_cast<uint4*>(g_ilv + ((long long)row * GS + w) * VOXH);
        dst[0] = *reinterpret_cast<const uint4*>(&v[0]);
        dst[1] = *reinterpret_cast<const uint4*>(&v[4]);
    }
}

// ---------------------------------------------------------------------------
// Kernel 2: WARP-COOPERATIVE trilinear gather.
// 4 lanes per point, 8 points per warp. Each LDG.128 loads one 64B (d,h)
// row-pair for all 8 points cooperatively (lanes 4p..4p+3 = 4 x 16B chunks),
// so per instruction the warp touches ~12 lines instead of 32.
//   chunk j=0: w0 voxel ch0-7   | j=1: w0 voxel ch8-11+pad
//   chunk j=2: w1 voxel ch0-7   | j=3: w1 voxel ch8-11+pad
// After accumulating the 4 pairs, shfl.xor(2) combines w0+w1 halves.
// ---------------------------------------------------------------------------
__global__ void __launch_bounds__(256) trilerp_kernel(
    const float* __restrict__ xyz,
    const float* __restrict__ xyz_min,
    const float* __restrict__ xyz_max,
    float* __restrict__ out,
    int N)
{
    const int warp_g = (blockIdx.x * blockDim.x + threadIdx.x) >> 5;
    const int lane = threadIdx.x & 31;
    const int sub = lane >> 2;            // point-in-group 0..7
    const int j   = lane & 3;             // 16B chunk 0..3

    int n = warp_g * 8 + sub;
    const bool valid = (n < N);
    n = min(n, N - 1);                    // clamp: loads stay in-bounds, stores predicated

    const float px = xyz[3 * n + 0];
    const float py = xyz[3 * n + 1];
    const float pz = xyz[3 * n + 2];

    const float mn0 = __ldg(&xyz_min[0]);
    const float mn1 = __ldg(&xyz_min[1]);
    const float mn2 = __ldg(&xyz_min[2]);
    const float mx0 = __ldg(&xyz_max[0]);
    const float mx1 = __ldg(&xyz_max[1]);
    const float mx2 = __ldg(&xyz_max[2]);

    const float hi  = (float)(GS - 1);    // 159
    const float hi2 = (float)(GS - 2);    // 158

    float ud = (px - mn0) * (hi / (mx0 - mn0));
    ud = fminf(fmaxf(ud, 0.0f), hi);
    float d0f = fminf(floorf(ud), hi2);
    float fd = ud - d0f;
    int d0 = (int)d0f;

    float uh = (py - mn1) * (hi / (mx1 - mn1));
    uh = fminf(fmaxf(uh, 0.0f), hi);
    float h0f = fminf(floorf(uh), hi2);
    float fh = uh - h0f;
    int h0 = (int)h0f;

    float uw = (pz - mn2) * (hi / (mx2 - mn2));
    uw = fminf(fmaxf(uw, 0.0f), hi);
    float w0f = fminf(floorf(uw), hi2);
    float fw = uw - w0f;
    int w0 = (int)w0f;

    const u32 b0 = ((u32)(d0 * GS + h0) * GS + (u32)w0) * (u32)VOXB + (u32)j * 16u;

    const float omfd = 1.0f - fd, omfh = 1.0f - fh, omfw = 1.0f - fw;
    const float coef[4] = { omfd * omfh, omfd * fh, fd * omfh, fd * fh };
    const float wsel = (j < 2) ? omfw : fw;   // this lane's w0/w1 side
    const u32 qoff[4] = { 0u, (u32)ROWB, (u32)SLABB, (u32)(SLABB + ROWB) };

    // Batch the 4 cooperative LDG.128 for MLP.
    uint4 r[4];
#pragma unroll
    for (int q = 0; q < 4; q++)
        r[q] = *reinterpret_cast<const uint4*>(
            reinterpret_cast<const char*>(g_ilv) + (b0 + qoff[q]));

    float acc[8];
#pragma unroll
    for (int k = 0; k < 8; k++) acc[k] = 0.0f;

#pragma unroll
    for (int q = 0; q < 4; q++) {
        const float w = coef[q] * wsel;
        const __half2* hp = reinterpret_cast<const __half2*>(&r[q]);
#pragma unroll
        for (int i = 0; i < 4; i++) {
            float2 f = __half22float2(hp[i]);
            acc[2 * i + 0] += w * f.x;
            acc[2 * i + 1] += w * f.y;
        }
    }

    // Combine w0 (lanes j=0,1) with w1 (lanes j=2,3): xor lane by 2.
#pragma unroll
    for (int k = 0; k < 8; k++)
        acc[k] += __shfl_xor_sync(0xffffffffu, acc[k], 2);

    if (valid) {
        float* o = out + (long long)n * GC;
        if (j == 0) {
            *reinterpret_cast<float4*>(o)     = make_float4(acc[0], acc[1], acc[2], acc[3]);
            *reinterpret_cast<float4*>(o + 4) = make_float4(acc[4], acc[5], acc[6], acc[7]);
        } else if (j == 1) {
            *reinterpret_cast<float4*>(o + 8) = make_float4(acc[0], acc[1], acc[2], acc[3]);
        }
    }
}

// ---------------------------------------------------------------------------
// kernel_launch
// Inputs (metadata order): xyz [N,3] f32, grid [1,12,160,160,160] f32,
//                          xyz_min [3] f32, xyz_max [3] f32
// Output: [N, 12] f32
// ---------------------------------------------------------------------------
extern "C" void kernel_launch(void* const* d_in, const int* in_sizes, int n_in,
                              void* d_out, int out_size) {
    const float* xyz     = (const float*)d_in[0];
    const float* grid    = (const float*)d_in[1];
    const float* xyz_min = (const float*)d_in[2];
    const float* xyz_max = (const float*)d_in[3];
    float* out = (float*)d_out;

    const int N = in_sizes[0] / 3;

    transpose_ilv_kernel<<<GS * GS, 256>>>(grid);

    // 8 points per warp, 8 warps per block -> 64 points per block
    const int blocks = (N + 63) / 64;
    trilerp_kernel<<<blocks, 256>>>(xyz, xyz_min, xyz_max, out, N);
}